// round 10
// baseline (speedup 1.0000x reference)
#include <cuda_runtime.h>
#include <cuda_bf16.h>
#include <cstdint>

#define NMAX 100000
#define EMAX 1600000

// Scratch (device globals — allocation-free per harness rules)
__device__ float  g_H[NMAX * 128];     // node features (post-layer, fp32)
__device__ float  g_M[NMAX * 128];     // messages: (h @ W) * dinv[row], fp32
__device__ float  g_dinv[NMAX];
__device__ int    g_deg[NMAX];
__device__ int    g_cur[NMAX];
__device__ int    g_rptr[NMAX + 1];
__device__ int    g_col[EMAX];
__device__ int    g_src[EMAX];
__device__ int    g_dst[EMAX];
__device__ int    g_batch[NMAX];
__device__ int    g_is64;

// Pre-converted bf16 W images, B-layout [n][k] with rows padded to 136 halves.
#define BROW 136
__device__ __align__(16) unsigned short g_Wb[3][2][128 * BROW];

__device__ __forceinline__ uint32_t packbf(float x0, float x1) {
    return ((uint32_t)__bfloat16_as_ushort(__float2bfloat16(x1)) << 16)
         |  (uint32_t)__bfloat16_as_ushort(__float2bfloat16(x0));
}

__device__ __forceinline__ uint32_t smem_u32(const void* p) {
    uint32_t a;
    asm("{ .reg .u64 t; cvta.to.shared.u64 t, %1; cvt.u32.u64 %0, t; }" : "=r"(a) : "l"(p));
    return a;
}

// ===================== init: zero counters + dtype probe + W conversion (fused) =====================
__global__ void k_init(const void* edge, const float* __restrict__ conv_w, int N) {
    int i = blockIdx.x * blockDim.x + threadIdx.x;
    if (i < N) { g_deg[i] = 0; g_cur[i] = 0; }

    if (blockIdx.x == gridDim.x - 1 && threadIdx.x == 0) {
        const long long* e64 = (const long long*)edge;
        int ok = 1;
        for (int q = 0; q < 8; q++) {
            long long v = e64[q];
            if (v < 0 || v >= (1LL << 31)) ok = 0;
        }
        g_is64 = ok;
    }

    if (blockIdx.x < 24) {
        int g = blockIdx.x * 2 + (threadIdx.x >> 7);   // 0..47
        int l = g >> 4;
        int c = (g & 15) * 8;
        int n = threadIdx.x & 127;
        const float* W = conv_w + (size_t)l * 16384;
        uint32_t hi[4], lo[4];
#pragma unroll
        for (int j = 0; j < 4; j++) {
            float v0 = W[(size_t)(c + 2 * j) * 128 + n];
            float v1 = W[(size_t)(c + 2 * j + 1) * 128 + n];
            float h0 = __bfloat162float(__float2bfloat16(v0));
            float h1 = __bfloat162float(__float2bfloat16(v1));
            hi[j] = packbf(v0, v1);
            lo[j] = packbf(v0 - h0, v1 - h1);
        }
        *(uint4*)&g_Wb[l][0][n * BROW + c] = make_uint4(hi[0], hi[1], hi[2], hi[3]);
        *(uint4*)&g_Wb[l][1][n * BROW + c] = make_uint4(lo[0], lo[1], lo[2], lo[3]);
    }
}

// ===================== edge convert + degree histogram (fused) =====================
__global__ void k_cvt_edge_deg(const void* edge, int E, int N) {
    int i = blockIdx.x * blockDim.x + threadIdx.x;
    if (i >= E) return;
    int s, d;
    if (g_is64) {
        const long long* e = (const long long*)edge;
        s = (int)e[i];
        d = (int)e[E + i];
    } else {
        const int* e = (const int*)edge;
        s = e[i];
        d = e[E + i];
    }
    g_src[i] = s;
    g_dst[i] = d;
    if ((unsigned)d < (unsigned)N) atomicAdd(&g_deg[d], 1);
}

__global__ void k_cvt_batch(const void* batch, int N) {
    int i = blockIdx.x * blockDim.x + threadIdx.x;
    if (i >= N) return;
    g_batch[i] = g_is64 ? (int)((const long long*)batch)[i]
                        : ((const int*)batch)[i];
}

// ===================== exclusive scan -> g_rptr + dinv (fused, single block) =====================
__global__ void __launch_bounds__(1024) k_scan_dinv(int N) {
    __shared__ int ssum[1024];
    int t = threadIdx.x;
    int per = (N + 1023) / 1024;
    int begin = t * per;
    int end   = begin + per; if (end > N) end = N; if (begin > N) begin = N;
    int s = 0;
    for (int i = begin; i < end; i++) {
        int dg = g_deg[i];
        s += dg;
        g_dinv[i] = rsqrtf((float)(dg + 1));   // +1 self-loop
    }
    ssum[t] = s;
    __syncthreads();
    for (int off = 1; off < 1024; off <<= 1) {
        int v = (t >= off) ? ssum[t - off] : 0;
        __syncthreads();
        ssum[t] += v;
        __syncthreads();
    }
    int run = (t == 0) ? 0 : ssum[t - 1];
    for (int i = begin; i < end; i++) { g_rptr[i] = run; run += g_deg[i]; }
    if (t == 1023) g_rptr[N] = run;
}

// ===================== CSR fill =====================
__global__ void k_fill(int E, int N) {
    int i = blockIdx.x * blockDim.x + threadIdx.x;
    if (i >= E) return;
    unsigned d = (unsigned)g_dst[i];
    unsigned s = (unsigned)g_src[i];
    if (d >= (unsigned)N || s >= (unsigned)N) return;
    int pos = atomicAdd(&g_cur[d], 1);
    g_col[g_rptr[d] + pos] = (int)s;
}

// ===================== mma.sync GEMM: M = (Hin @ W) * dinv[row] =====================
// CTA: 512 threads (16 warps), tile 128(M)x128(N), K=128. Warp tile 32x32.
// SMEM (halves, rows padded to BROW=136): Ah | Al | Bh | Bl.
// Split bf16: acc = Ah*Bh + Ah*Bl + Al*Bh; fragments via ldmatrix.x4.
#define TILE_H (128 * BROW)

#define MMA_BF16(ACC, A0, A1, A2, A3, B0, B1) \
    asm volatile( \
        "mma.sync.aligned.m16n8k16.row.col.f32.bf16.bf16.f32 " \
        "{%0,%1,%2,%3}, {%4,%5,%6,%7}, {%8,%9}, {%0,%1,%2,%3};" \
        : "+f"((ACC)[0]), "+f"((ACC)[1]), "+f"((ACC)[2]), "+f"((ACC)[3]) \
        : "r"(A0), "r"(A1), "r"(A2), "r"(A3), "r"(B0), "r"(B1))

#define LDSM_X4(R, ADDR) \
    asm volatile("ldmatrix.sync.aligned.m8n8.x4.shared.b16 {%0,%1,%2,%3}, [%4];" \
        : "=r"((R)[0]), "=r"((R)[1]), "=r"((R)[2]), "=r"((R)[3]) : "r"(ADDR))

__global__ void __launch_bounds__(512, 1) k_gemm_mma(const float* __restrict__ xin,
                                                     int layer, int N, int useH) {
    extern __shared__ unsigned short sm[];
    const float* __restrict__ Hin = useH ? (const float*)g_H : xin;

    int tid  = threadIdx.x;
    int lane = tid & 31;
    int wid  = tid >> 5;
    int row0 = blockIdx.x * 128;

    unsigned short* Ah = sm;
    unsigned short* Al = sm + TILE_H;
    unsigned short* Bh = sm + 2 * TILE_H;
    unsigned short* Bl = sm + 3 * TILE_H;

    // ---- stage A: fp32 -> bf16 hi/lo ----
#pragma unroll
    for (int i = 0; i < 4; i++) {
        int j = tid + i * 512;           // 0..2047, each handles 8 floats
        int r = j >> 4;
        int c = (j & 15) << 3;
        float v[8];
        if (row0 + r < N) {
            float4 a = *(const float4*)(Hin + (size_t)(row0 + r) * 128 + c);
            float4 b = *(const float4*)(Hin + (size_t)(row0 + r) * 128 + c + 4);
            v[0] = a.x; v[1] = a.y; v[2] = a.z; v[3] = a.w;
            v[4] = b.x; v[5] = b.y; v[6] = b.z; v[7] = b.w;
        } else {
#pragma unroll
            for (int q = 0; q < 8; q++) v[q] = 0.f;
        }
        uint32_t hi[4], lo[4];
#pragma unroll
        for (int q = 0; q < 4; q++) {
            float x0 = v[2 * q], x1 = v[2 * q + 1];
            float h0 = __bfloat162float(__float2bfloat16(x0));
            float h1 = __bfloat162float(__float2bfloat16(x1));
            hi[q] = packbf(x0, x1);
            lo[q] = packbf(x0 - h0, x1 - h1);
        }
        *(uint4*)&Ah[r * BROW + c] = make_uint4(hi[0], hi[1], hi[2], hi[3]);
        *(uint4*)&Al[r * BROW + c] = make_uint4(lo[0], lo[1], lo[2], lo[3]);
    }

    // ---- copy W images ----
    {
        const uint4* wh = (const uint4*)g_Wb[layer][0];
        const uint4* wl = (const uint4*)g_Wb[layer][1];
        uint4* bh = (uint4*)Bh;
        uint4* bl = (uint4*)Bl;
        for (int j = tid; j < (TILE_H / 8); j += 512) {   // 2176 uint4
            bh[j] = wh[j];
            bl[j] = wl[j];
        }
    }
    __syncthreads();

    // warp tile: 32 rows x 32 cols
    int wm = wid & 3;            // 4 m-groups of 32 rows
    int wn = wid >> 2;           // 4 n-groups of 32 cols
    int m0 = wm * 32;
    int n0 = wn * 32;
    int gid = lane >> 2;
    int tig = lane & 3;

    // ldmatrix per-lane source row/col selection:
    // lanes 0-7: mat0 (rows +0, k+0), 8-15: mat1 (rows +8, k+0),
    // 16-23: mat2 (rows +0, k+8), 24-31: mat3 (rows +8, k+8)
    int l8   = lane & 7;
    int rsel = (lane >> 3) & 1;
    int ksel = (lane >> 4) & 1;
    int rowA0 = m0 + l8 + rsel * 8;          // mf=0 block rows
    int rowA1 = m0 + 16 + l8 + rsel * 8;     // mf=1
    int rowB0 = n0 + l8 + rsel * 8;          // nf pair {0,1}
    int rowB1 = n0 + 16 + l8 + rsel * 8;     // nf pair {2,3}
    int koff  = ksel * 8;

    float acc[2][4][4];
#pragma unroll
    for (int mf = 0; mf < 2; mf++)
#pragma unroll
        for (int nf = 0; nf < 4; nf++)
#pragma unroll
            for (int q = 0; q < 4; q++) acc[mf][nf][q] = 0.f;

#pragma unroll
    for (int s = 0; s < 3; s++) {
        const unsigned short* Asel = (s == 2) ? Al : Ah;
        const unsigned short* Bsel = (s == 1) ? Bl : Bh;
        uint32_t aA0 = smem_u32(Asel + rowA0 * BROW + koff);
        uint32_t aA1 = smem_u32(Asel + rowA1 * BROW + koff);
        uint32_t aB0 = smem_u32(Bsel + rowB0 * BROW + koff);
        uint32_t aB1 = smem_u32(Bsel + rowB1 * BROW + koff);
#pragma unroll
        for (int k = 0; k < 8; k++) {
            uint32_t kb = k * 32;   // 16 halves per k-step
            uint32_t a0[4], a1[4], b0[4], b1[4];
            LDSM_X4(a0, aA0 + kb);
            LDSM_X4(a1, aA1 + kb);
            LDSM_X4(b0, aB0 + kb);   // regs: {b[0][0], b[1][0], b[0][1], b[1][1]}
            LDSM_X4(b1, aB1 + kb);   // regs: {b[2][0], b[3][0], b[2][1], b[3][1]}
            MMA_BF16(acc[0][0], a0[0], a0[1], a0[2], a0[3], b0[0], b0[2]);
            MMA_BF16(acc[0][1], a0[0], a0[1], a0[2], a0[3], b0[1], b0[3]);
            MMA_BF16(acc[0][2], a0[0], a0[1], a0[2], a0[3], b1[0], b1[2]);
            MMA_BF16(acc[0][3], a0[0], a0[1], a0[2], a0[3], b1[1], b1[3]);
            MMA_BF16(acc[1][0], a1[0], a1[1], a1[2], a1[3], b0[0], b0[2]);
            MMA_BF16(acc[1][1], a1[0], a1[1], a1[2], a1[3], b0[1], b0[3]);
            MMA_BF16(acc[1][2], a1[0], a1[1], a1[2], a1[3], b1[0], b1[2]);
            MMA_BF16(acc[1][3], a1[0], a1[1], a1[2], a1[3], b1[1], b1[3]);
        }
    }

    // ---- epilogue: D * dinv -> g_M (fp32) ----
#pragma unroll
    for (int mf = 0; mf < 2; mf++) {
        int r1 = row0 + m0 + mf * 16 + gid;
        int r2 = r1 + 8;
        float dv1 = (r1 < N) ? g_dinv[r1] : 0.f;
        float dv2 = (r2 < N) ? g_dinv[r2] : 0.f;
#pragma unroll
        for (int nf = 0; nf < 4; nf++) {
            int c = n0 + nf * 8 + tig * 2;
            if (r1 < N)
                *(float2*)(g_M + (size_t)r1 * 128 + c) =
                    make_float2(acc[mf][nf][0] * dv1, acc[mf][nf][1] * dv1);
            if (r2 < N)
                *(float2*)(g_M + (size_t)r2 * 128 + c) =
                    make_float2(acc[mf][nf][2] * dv2, acc[mf][nf][3] * dv2);
        }
    }
}

// ===================== gather aggregation + bias + relu (fp32 messages) =====================
// H[d] = relu( dinv[d] * ( M[d] + sum_{e: dst=d} M[src_e] ) + b )
__global__ void __launch_bounds__(256) k_gather(const float* __restrict__ b, int N) {
    int w = (blockIdx.x * 256 + threadIdx.x) >> 5;
    if (w >= N) return;
    int lane = threadIdx.x & 31;

    int s0 = g_rptr[w], s1 = g_rptr[w + 1];
    float dv = g_dinv[w];
    const float4* M4 = (const float4*)g_M;

    float4 acc = __ldg(&M4[(size_t)w * 32 + lane]);   // self-loop message (pre-scaled by dinv[w])

    int e = s0;
    for (; e + 7 < s1; e += 8) {
        int si[8];
#pragma unroll
        for (int q = 0; q < 8; q++) si[q] = __ldg(&g_col[e + q]);
        float4 v[8];
#pragma unroll
        for (int q = 0; q < 8; q++) v[q] = __ldg(&M4[(size_t)si[q] * 32 + lane]);
#pragma unroll
        for (int q = 0; q < 8; q++) {
            acc.x += v[q].x; acc.y += v[q].y; acc.z += v[q].z; acc.w += v[q].w;
        }
    }
    for (; e + 3 < s1; e += 4) {
        int si[4];
#pragma unroll
        for (int q = 0; q < 4; q++) si[q] = __ldg(&g_col[e + q]);
#pragma unroll
        for (int q = 0; q < 4; q++) {
            float4 v = __ldg(&M4[(size_t)si[q] * 32 + lane]);
            acc.x += v.x; acc.y += v.y; acc.z += v.z; acc.w += v.w;
        }
    }
    for (; e < s1; e++) {
        float4 v = __ldg(&M4[(size_t)__ldg(&g_col[e]) * 32 + lane]);
        acc.x += v.x; acc.y += v.y; acc.z += v.z; acc.w += v.w;
    }

    float4 bb = ((const float4*)b)[lane];
    float4 o;
    o.x = fmaxf(acc.x * dv + bb.x, 0.f);
    o.y = fmaxf(acc.y * dv + bb.y, 0.f);
    o.z = fmaxf(acc.z * dv + bb.z, 0.f);
    o.w = fmaxf(acc.w * dv + bb.w, 0.f);
    ((float4*)g_H)[(size_t)w * 32 + lane] = o;
}

// ===================== fused pooling + output linear =====================
__global__ void __launch_bounds__(128) k_pool_out(const float* __restrict__ out_w,
                                                  const float* __restrict__ out_b,
                                                  float* __restrict__ out, int N) {
    int g = blockIdx.x;
    int d = threadIdx.x;

    int lo, hi;
    { int a = 0, b = N; while (a < b) { int m = (a + b) >> 1; if (g_batch[m] < g) a = m + 1; else b = m; } lo = a; }
    { int a = lo, b = N; while (a < b) { int m = (a + b) >> 1; if (g_batch[m] < g + 1) a = m + 1; else b = m; } hi = a; }

    float s = 0.f, mx = 0.f;   // relu output >= 0: max init 0 matches segment_max for non-empty segments
    for (int n = lo; n < hi; n++) {
        float v = g_H[(size_t)n * 128 + d];
        s += v;
        mx = fmaxf(mx, v);
    }
    float cnt  = fmaxf((float)(hi - lo), 1.f);
    float mean = s / cnt;

    __shared__ float sp[128][10];
#pragma unroll
    for (int j = 0; j < 10; j++)
        sp[d][j] = mx * out_w[d * 10 + j]
                 + mean * out_w[(128 + d) * 10 + j]
                 + s * out_w[(256 + d) * 10 + j];
    __syncthreads();

    if (d < 10) {
        float r = 0.f;
        for (int i = 0; i < 128; i++) r += sp[i][d];
        out[g * 10 + d] = r + out_b[d];
    }
}

// ===================== launch =====================
extern "C" void kernel_launch(void* const* d_in, const int* in_sizes, int n_in,
                              void* d_out, int out_size) {
    const float* x      = (const float*)d_in[0];
    const void*  edge   = d_in[1];
    const void*  batch  = d_in[2];
    const float* conv_w = (const float*)d_in[3];
    const float* conv_b = (const float*)d_in[4];
    const float* out_w  = (const float*)d_in[5];
    const float* out_b  = (const float*)d_in[6];
    float*       out    = (float*)d_out;

    int N = in_sizes[0] / 128;
    int E = in_sizes[1] / 2;

    const int SMEM_BYTES = 4 * TILE_H * 2;   // 139264
    static bool attr_done = false;
    if (!attr_done) {
        cudaFuncSetAttribute(k_gemm_mma, cudaFuncAttributeMaxDynamicSharedMemorySize, SMEM_BYTES);
        attr_done = true;
    }

    int tiles = (N + 127) / 128;

    // Launch order keeps k_gemm_mma at slot 4 (the launch ncu captures).
    k_init<<<(N + 255) / 256, 256>>>(edge, conv_w, N);             // 1: zero + probe + wconv
    k_cvt_edge_deg<<<(E + 255) / 256, 256>>>(edge, E, N);          // 2
    k_scan_dinv<<<1, 1024>>>(N);                                   // 3
    k_gemm_mma<<<tiles, 512, SMEM_BYTES>>>(x, 0, N, 0);            // 4  <- profiled
    k_fill<<<(E + 255) / 256, 256>>>(E, N);                        // 5
    k_gather<<<(N * 32 + 255) / 256, 256>>>(conv_b + 0 * 128, N);  // 6
    for (int l = 1; l < 3; l++) {
        k_gemm_mma<<<tiles, 512, SMEM_BYTES>>>(x, l, N, 1);
        k_gather<<<(N * 32 + 255) / 256, 256>>>(conv_b + l * 128, N);
    }
    k_cvt_batch<<<(N + 255) / 256, 256>>>(batch, N);
    k_pool_out<<<256, 128>>>(out_w, out_b, out, N);
}

// round 12
// speedup vs baseline: 1.3536x; 1.3536x over previous
#include <cuda_runtime.h>
#include <cuda_bf16.h>
#include <cstdint>

#define NMAX 100000
#define EMAX 1600000
#define SF_GRID 96          // scanfill blocks (all co-resident on 148 SMs)

// Scratch (device globals — allocation-free per harness rules)
__device__ float  g_S[NMAX * 128];     // aggregated features S = A_hat * H
__device__ float  g_P[NMAX * 128];     // P = dinv .* H (layers 0,1); raw H3 (layer 2, for pool)
__device__ float  g_dinv[NMAX];
__device__ int    g_deg[NMAX];         // zeroed by previous call's pool (BSS zero on call 1)
__device__ int    g_cur[NMAX];
__device__ int    g_rptr[NMAX + 1];
__device__ int    g_col[EMAX];
__device__ int    g_blocksum[128];
__device__ int    g_done;
__device__ int    g_is64;

// Pre-converted bf16 W images, B-layout [n][k] with rows padded to 136 halves.
#define BROW 136
__device__ __align__(16) unsigned short g_Wb[3][2][128 * BROW];

__device__ __forceinline__ uint32_t packbf(float x0, float x1) {
    return ((uint32_t)__bfloat16_as_ushort(__float2bfloat16(x1)) << 16)
         |  (uint32_t)__bfloat16_as_ushort(__float2bfloat16(x0));
}

// ===================== L1: probe + W conversion + flag reset =====================
__global__ void k_init(const void* edge, const float* __restrict__ conv_w) {
    if (blockIdx.x == 24) {
        int t = threadIdx.x;
        if (t == 0) {
            const long long* e64 = (const long long*)edge;
            int ok = 1;
            for (int q = 0; q < 8; q++) {
                long long v = e64[q];
                if (v < 0 || v >= (1LL << 31)) ok = 0;
            }
            g_is64 = ok;
            g_done = 0;
        }
        if (t < 128) g_blocksum[t] = -1;
        return;
    }
    // blocks 0..23: W -> bf16 hi/lo images, B layout [n][k]
    int g = blockIdx.x * 2 + (threadIdx.x >> 7);   // 0..47
    int l = g >> 4;
    int c = (g & 15) * 8;
    int n = threadIdx.x & 127;
    const float* W = conv_w + (size_t)l * 16384;
    uint32_t hi[4], lo[4];
#pragma unroll
    for (int j = 0; j < 4; j++) {
        float v0 = W[(size_t)(c + 2 * j) * 128 + n];
        float v1 = W[(size_t)(c + 2 * j + 1) * 128 + n];
        float h0 = __bfloat162float(__float2bfloat16(v0));
        float h1 = __bfloat162float(__float2bfloat16(v1));
        hi[j] = packbf(v0, v1);
        lo[j] = packbf(v0 - h0, v1 - h1);
    }
    *(uint4*)&g_Wb[l][0][n * BROW + c] = make_uint4(hi[0], hi[1], hi[2], hi[3]);
    *(uint4*)&g_Wb[l][1][n * BROW + c] = make_uint4(lo[0], lo[1], lo[2], lo[3]);
}

// ===================== L2: degree histogram (direct dtype read) =====================
__global__ void k_deg(const void* edge, int E, int N) {
    int i = blockIdx.x * blockDim.x + threadIdx.x;
    if (i >= E) return;
    int d = g_is64 ? (int)((const long long*)edge)[E + i]
                   : ((const int*)edge)[E + i];
    if ((unsigned)d < (unsigned)N) atomicAdd(&g_deg[d], 1);
}

// ===================== L3: fused scan (decoupled lookback) + dinv + CSR fill =====================
// SF_GRID blocks x 1024 threads, all co-resident -> spin barriers are safe.
// Each thread owns TWO CONSECUTIVE elements (2t, 2t+1) so rptr stays element-ordered.
__global__ void __launch_bounds__(1024) k_scanfill(const void* edge, int E, int N) {
    __shared__ int ssum[1024];
    __shared__ int sbs[SF_GRID];
    __shared__ int sh_pref, sh_tot;

    int b = blockIdx.x, t = threadIdx.x;
    int C = (N + SF_GRID - 1) / SF_GRID;       // <= 2048 for N <= 196608
    int base = b * C;
    int lim  = min(base + C, N);
    int i0 = base + 2 * t;                     // consecutive pair (order-correct scan)
    int i1 = i0 + 1;
    int d0 = (i0 < lim) ? g_deg[i0] : 0;
    int d1 = (i1 < lim) ? g_deg[i1] : 0;
    int part = d0 + d1;

    ssum[t] = part;
    __syncthreads();
    for (int off = 1; off < 1024; off <<= 1) {
        int v = (t >= off) ? ssum[t - off] : 0;
        __syncthreads();
        ssum[t] += v;
        __syncthreads();
    }
    int incl = ssum[t];
    int agg  = ssum[1023];

    if (t == 0) atomicExch(&g_blocksum[b], agg);   // publish (atomic => L2-visible)

    // lookback: wait for all aggregates
    if (t < SF_GRID) {
        int v;
        do { v = atomicAdd(&g_blocksum[t], 0); if (v != -1) break; __nanosleep(64); } while (1);
        sbs[t] = v;
    }
    __syncthreads();
    if (t == 0) {
        int p = 0, tot = 0;
        for (int j = 0; j < SF_GRID; j++) { if (j < b) p += sbs[j]; tot += sbs[j]; }
        sh_pref = p; sh_tot = tot;
    }
    __syncthreads();

    int excl = sh_pref + incl - part;          // exclusive prefix of element i0
    if (i0 < lim) {
        g_rptr[i0] = excl;
        atomicExch(&g_cur[i0], excl);          // atomic store: visible to fill phase
        g_dinv[i0] = rsqrtf((float)(d0 + 1));  // +1 self-loop
    }
    if (i1 < lim) {
        int e1 = excl + d0;
        g_rptr[i1] = e1;
        atomicExch(&g_cur[i1], e1);
        g_dinv[i1] = rsqrtf((float)(d1 + 1));
    }
    if (b == SF_GRID - 1 && t == 0) g_rptr[N] = sh_tot;

    // grid barrier before fill
    __threadfence();
    __syncthreads();
    if (t == 0) {
        atomicAdd(&g_done, 1);
        while (atomicAdd(&g_done, 0) < SF_GRID) __nanosleep(128);
    }
    __syncthreads();

    // fill: bucket src by dst (grid-stride over edges)
    int is64 = g_is64;
    const long long* e64 = (const long long*)edge;
    const int*       e32 = (const int*)edge;
    for (int e = b * 1024 + t; e < E; e += SF_GRID * 1024) {
        int s, d;
        if (is64) { s = (int)e64[e]; d = (int)e64[E + e]; }
        else      { s = e32[e];      d = e32[E + e]; }
        if ((unsigned)d < (unsigned)N) {
            int pos = atomicAdd(&g_cur[d], 1);
            g_col[pos] = ((unsigned)s < (unsigned)N) ? s : 0;
        }
    }
}

// ===================== gather: S[d] = dinv[d]*(P[d] + sum_{e:dst=d} P[src]) =====================
// L0: P computed on the fly from x (P[i] = dinv[i]*x[i]); else P = g_P (pre-scaled by gemm).
template<bool L0>
__global__ void __launch_bounds__(256) k_gather(const float* __restrict__ xin, int N) {
    int w = (blockIdx.x * 256 + threadIdx.x) >> 5;
    if (w >= N) return;
    int lane = threadIdx.x & 31;

    int s0 = g_rptr[w], s1 = g_rptr[w + 1];
    float dv = g_dinv[w];
    const float4* B4 = L0 ? (const float4*)xin : (const float4*)g_P;

    float4 acc = B4[(size_t)w * 32 + lane];       // self term
    if (L0) { acc.x *= dv; acc.y *= dv; acc.z *= dv; acc.w *= dv; }

    int e = s0;
    for (; e + 3 < s1; e += 4) {
        int sa = g_col[e], sb = g_col[e + 1], sc = g_col[e + 2], sd = g_col[e + 3];
        float4 va = B4[(size_t)sa * 32 + lane];
        float4 vb = B4[(size_t)sb * 32 + lane];
        float4 vc = B4[(size_t)sc * 32 + lane];
        float4 vd = B4[(size_t)sd * 32 + lane];
        if (L0) {
            float fa = g_dinv[sa], fb = g_dinv[sb], fc = g_dinv[sc], fd = g_dinv[sd];
            va.x *= fa; va.y *= fa; va.z *= fa; va.w *= fa;
            vb.x *= fb; vb.y *= fb; vb.z *= fb; vb.w *= fb;
            vc.x *= fc; vc.y *= fc; vc.z *= fc; vc.w *= fc;
            vd.x *= fd; vd.y *= fd; vd.z *= fd; vd.w *= fd;
        }
        acc.x += va.x + vb.x + vc.x + vd.x;
        acc.y += va.y + vb.y + vc.y + vd.y;
        acc.z += va.z + vb.z + vc.z + vd.z;
        acc.w += va.w + vb.w + vc.w + vd.w;
    }
    for (; e < s1; e++) {
        int s = g_col[e];
        float4 v = B4[(size_t)s * 32 + lane];
        if (L0) { float f = g_dinv[s]; v.x *= f; v.y *= f; v.z *= f; v.w *= f; }
        acc.x += v.x; acc.y += v.y; acc.z += v.z; acc.w += v.w;
    }

    acc.x *= dv; acc.y *= dv; acc.z *= dv; acc.w *= dv;
    ((float4*)g_S)[(size_t)w * 32 + lane] = acc;
}

// ===================== mma.sync GEMM (R7 core): out = relu(S @ W + b) =====================
// CTA: 256 threads (8 warps), tile 128x128, K=128. Split bf16 (3 products), per-(s,k) loads.
// Epilogue: bias+relu fused; layers 0,1 write P = dinv*out; layer 2 writes raw out (for pool).
#define TILE_H (128 * BROW)

__global__ void __launch_bounds__(256, 1) k_gemm_mma(int layer, const float* __restrict__ bias,
                                                     int N) {
    extern __shared__ unsigned short sm[];
    int tid  = threadIdx.x;
    int lane = tid & 31;
    int wid  = tid >> 5;
    int row0 = blockIdx.x * 128;

    unsigned short* Ah = sm;
    unsigned short* Al = sm + TILE_H;
    unsigned short* Bh = sm + 2 * TILE_H;
    unsigned short* Bl = sm + 3 * TILE_H;

    // ---- stage A = g_S: fp32 -> bf16 hi/lo ----
#pragma unroll
    for (int i = 0; i < 8; i++) {
        int j = tid + i * 256;
        int r = j >> 4;
        int c = (j & 15) << 3;
        float v[8];
        if (row0 + r < N) {
            float4 a = *(const float4*)(g_S + (size_t)(row0 + r) * 128 + c);
            float4 b = *(const float4*)(g_S + (size_t)(row0 + r) * 128 + c + 4);
            v[0] = a.x; v[1] = a.y; v[2] = a.z; v[3] = a.w;
            v[4] = b.x; v[5] = b.y; v[6] = b.z; v[7] = b.w;
        } else {
#pragma unroll
            for (int q = 0; q < 8; q++) v[q] = 0.f;
        }
        uint32_t hi[4], lo[4];
#pragma unroll
        for (int q = 0; q < 4; q++) {
            float x0 = v[2 * q], x1 = v[2 * q + 1];
            float h0 = __bfloat162float(__float2bfloat16(x0));
            float h1 = __bfloat162float(__float2bfloat16(x1));
            hi[q] = packbf(x0, x1);
            lo[q] = packbf(x0 - h0, x1 - h1);
        }
        *(uint4*)&Ah[r * BROW + c] = make_uint4(hi[0], hi[1], hi[2], hi[3]);
        *(uint4*)&Al[r * BROW + c] = make_uint4(lo[0], lo[1], lo[2], lo[3]);
    }

    // ---- copy W images ----
    {
        const uint4* wh = (const uint4*)g_Wb[layer][0];
        const uint4* wl = (const uint4*)g_Wb[layer][1];
        uint4* bh = (uint4*)Bh;
        uint4* bl = (uint4*)Bl;
        for (int j = tid; j < (TILE_H / 8); j += 256) {
            bh[j] = wh[j];
            bl[j] = wl[j];
        }
    }
    __syncthreads();

    int wm = wid & 3;
    int wn = wid >> 2;
    int m0 = wm * 32;
    int n0 = wn * 64;
    int gid = lane >> 2;
    int tig = lane & 3;

    float acc[2][8][4];
#pragma unroll
    for (int mf = 0; mf < 2; mf++)
#pragma unroll
        for (int nf = 0; nf < 8; nf++)
#pragma unroll
            for (int q = 0; q < 4; q++) acc[mf][nf][q] = 0.f;

    for (int s = 0; s < 3; s++) {
        const unsigned short* Asel = (s == 2) ? Al : Ah;
        const unsigned short* Bsel = (s == 1) ? Bl : Bh;
#pragma unroll
        for (int k = 0; k < 8; k++) {
            int k0 = k * 16;
            uint32_t a[2][4];
#pragma unroll
            for (int mf = 0; mf < 2; mf++) {
                int rr = m0 + mf * 16;
                a[mf][0] = *(const uint32_t*)&Asel[(rr + gid)     * BROW + k0 + tig * 2];
                a[mf][1] = *(const uint32_t*)&Asel[(rr + gid + 8) * BROW + k0 + tig * 2];
                a[mf][2] = *(const uint32_t*)&Asel[(rr + gid)     * BROW + k0 + 8 + tig * 2];
                a[mf][3] = *(const uint32_t*)&Asel[(rr + gid + 8) * BROW + k0 + 8 + tig * 2];
            }
            uint32_t b[8][2];
#pragma unroll
            for (int nf = 0; nf < 8; nf++) {
                int n = n0 + nf * 8 + gid;
                b[nf][0] = *(const uint32_t*)&Bsel[n * BROW + k0 + tig * 2];
                b[nf][1] = *(const uint32_t*)&Bsel[n * BROW + k0 + 8 + tig * 2];
            }
#pragma unroll
            for (int mf = 0; mf < 2; mf++)
#pragma unroll
                for (int nf = 0; nf < 8; nf++) {
                    asm volatile(
                        "mma.sync.aligned.m16n8k16.row.col.f32.bf16.bf16.f32 "
                        "{%0,%1,%2,%3}, {%4,%5,%6,%7}, {%8,%9}, {%0,%1,%2,%3};"
                        : "+f"(acc[mf][nf][0]), "+f"(acc[mf][nf][1]),
                          "+f"(acc[mf][nf][2]), "+f"(acc[mf][nf][3])
                        : "r"(a[mf][0]), "r"(a[mf][1]), "r"(a[mf][2]), "r"(a[mf][3]),
                          "r"(b[nf][0]), "r"(b[nf][1]));
                }
        }
    }

    // ---- epilogue: bias + relu; P = out*dinv (layers 0,1) or raw out (layer 2) ----
#pragma unroll
    for (int mf = 0; mf < 2; mf++) {
        int r1 = row0 + m0 + mf * 16 + gid;
        int r2 = r1 + 8;
        float sc1 = 1.f, sc2 = 1.f;
        if (layer < 2) {
            sc1 = (r1 < N) ? g_dinv[r1] : 0.f;
            sc2 = (r2 < N) ? g_dinv[r2] : 0.f;
        }
#pragma unroll
        for (int nf = 0; nf < 8; nf++) {
            int c = n0 + nf * 8 + tig * 2;
            float2 bb = *(const float2*)(bias + c);
            if (r1 < N) {
                float v0 = fmaxf(acc[mf][nf][0] + bb.x, 0.f);
                float v1 = fmaxf(acc[mf][nf][1] + bb.y, 0.f);
                *(float2*)(g_P + (size_t)r1 * 128 + c) = make_float2(v0 * sc1, v1 * sc1);
            }
            if (r2 < N) {
                float v2 = fmaxf(acc[mf][nf][2] + bb.x, 0.f);
                float v3 = fmaxf(acc[mf][nf][3] + bb.y, 0.f);
                *(float2*)(g_P + (size_t)r2 * 128 + c) = make_float2(v2 * sc2, v3 * sc2);
            }
        }
    }
}

// ===================== pooling + output linear (+ zero g_deg for next call) =====================
__global__ void __launch_bounds__(128) k_pool_out(const void* __restrict__ batch,
                                                  const float* __restrict__ out_w,
                                                  const float* __restrict__ out_b,
                                                  float* __restrict__ out, int N) {
    // zero degree counters for the next replay (independent of the rest)
    for (int i = blockIdx.x * blockDim.x + threadIdx.x; i < N; i += gridDim.x * blockDim.x)
        g_deg[i] = 0;

    int g = blockIdx.x;
    int d = threadIdx.x;
    int is64 = g_is64;
    const long long* b64 = (const long long*)batch;
    const int*       b32 = (const int*)batch;

    int lo, hi;
    { int a = 0, b = N; while (a < b) { int m = (a + b) >> 1;
        int bm = is64 ? (int)b64[m] : b32[m];
        if (bm < g) a = m + 1; else b = m; } lo = a; }
    { int a = lo, b = N; while (a < b) { int m = (a + b) >> 1;
        int bm = is64 ? (int)b64[m] : b32[m];
        if (bm < g + 1) a = m + 1; else b = m; } hi = a; }

    float s = 0.f, mx = 0.f;   // relu output >= 0: max init 0 matches segment_max for non-empty segments
    for (int n = lo; n < hi; n++) {
        float v = g_P[(size_t)n * 128 + d];   // g_P holds raw H3 after layer 2
        s += v;
        mx = fmaxf(mx, v);
    }
    float cnt  = fmaxf((float)(hi - lo), 1.f);
    float mean = s / cnt;

    __shared__ float sp[128][10];
#pragma unroll
    for (int j = 0; j < 10; j++)
        sp[d][j] = mx * out_w[d * 10 + j]
                 + mean * out_w[(128 + d) * 10 + j]
                 + s * out_w[(256 + d) * 10 + j];
    __syncthreads();

    if (d < 10) {
        float r = 0.f;
        for (int i = 0; i < 128; i++) r += sp[i][d];
        out[g * 10 + d] = r + out_b[d];
    }
}

// ===================== launch =====================
extern "C" void kernel_launch(void* const* d_in, const int* in_sizes, int n_in,
                              void* d_out, int out_size) {
    const float* x      = (const float*)d_in[0];
    const void*  edge   = d_in[1];
    const void*  batch  = d_in[2];
    const float* conv_w = (const float*)d_in[3];
    const float* conv_b = (const float*)d_in[4];
    const float* out_w  = (const float*)d_in[5];
    const float* out_b  = (const float*)d_in[6];
    float*       out    = (float*)d_out;

    int N = in_sizes[0] / 128;
    int E = in_sizes[1] / 2;

    const int SMEM_BYTES = 4 * TILE_H * 2;   // 139264
    static bool attr_done = false;
    if (!attr_done) {
        cudaFuncSetAttribute(k_gemm_mma, cudaFuncAttributeMaxDynamicSharedMemorySize, SMEM_BYTES);
        attr_done = true;
    }

    int tiles = (N + 127) / 128;
    int gblk  = (N * 32 + 255) / 256;

    k_init<<<25, 256>>>(edge, conv_w);                            // 1
    k_deg<<<(E + 255) / 256, 256>>>(edge, E, N);                  // 2
    k_scanfill<<<SF_GRID, 1024>>>(edge, E, N);                    // 3
    k_gather<true><<<gblk, 256>>>(x, N);                          // 4  <- profiled
    k_gemm_mma<<<tiles, 256, SMEM_BYTES>>>(0, conv_b, N);         // 5
    k_gather<false><<<gblk, 256>>>(nullptr, N);                   // 6
    k_gemm_mma<<<tiles, 256, SMEM_BYTES>>>(1, conv_b + 128, N);   // 7
    k_gather<false><<<gblk, 256>>>(nullptr, N);                   // 8
    k_gemm_mma<<<tiles, 256, SMEM_BYTES>>>(2, conv_b + 256, N);   // 9
    k_pool_out<<<256, 128>>>(batch, out_w, out_b, out, N);        // 10
}

// round 13
// speedup vs baseline: 1.3879x; 1.0253x over previous
#include <cuda_runtime.h>
#include <cuda_bf16.h>
#include <cstdint>

#define NMAX 100000
#define EMAX 1600000
#define SF_GRID 96          // scanfill blocks (all co-resident on 148 SMs)

// Scratch (device globals — allocation-free per harness rules)
__device__ float  g_S[NMAX * 128];     // aggregated features S = A_hat * H
__device__ float  g_P[NMAX * 128];     // P = dinv .* H (layers 0,1); raw H3 (layer 2, for pool)
__device__ float  g_dinv[NMAX];
__device__ int    g_deg[NMAX];         // zeroed by previous call's pool (BSS zero on call 1)
__device__ int    g_cur[NMAX];
__device__ int    g_rptr[NMAX + 1];
__device__ int    g_col[EMAX];
__device__ int    g_blocksum[128];
__device__ int    g_done0, g_done1;
__device__ int    g_is64;

// Pre-converted bf16 W images, B-layout [n][k] with rows padded to 136 halves.
#define BROW 136
__device__ __align__(16) unsigned short g_Wb[3][2][128 * BROW];

__device__ __forceinline__ uint32_t packbf(float x0, float x1) {
    return ((uint32_t)__bfloat16_as_ushort(__float2bfloat16(x1)) << 16)
         |  (uint32_t)__bfloat16_as_ushort(__float2bfloat16(x0));
}

// ===================== L1: probe + W conversion + flag reset =====================
__global__ void k_init(const void* edge, const float* __restrict__ conv_w) {
    if (blockIdx.x == 24) {
        int t = threadIdx.x;
        if (t == 0) {
            const long long* e64 = (const long long*)edge;
            int ok = 1;
            for (int q = 0; q < 8; q++) {
                long long v = e64[q];
                if (v < 0 || v >= (1LL << 31)) ok = 0;
            }
            g_is64 = ok;
            g_done0 = 0;
            g_done1 = 0;
        }
        if (t < 128) g_blocksum[t] = -1;
        return;
    }
    // blocks 0..23: W -> bf16 hi/lo images, B layout [n][k]
    int g = blockIdx.x * 2 + (threadIdx.x >> 7);   // 0..47
    int l = g >> 4;
    int c = (g & 15) * 8;
    int n = threadIdx.x & 127;
    const float* W = conv_w + (size_t)l * 16384;
    uint32_t hi[4], lo[4];
#pragma unroll
    for (int j = 0; j < 4; j++) {
        float v0 = W[(size_t)(c + 2 * j) * 128 + n];
        float v1 = W[(size_t)(c + 2 * j + 1) * 128 + n];
        float h0 = __bfloat162float(__float2bfloat16(v0));
        float h1 = __bfloat162float(__float2bfloat16(v1));
        hi[j] = packbf(v0, v1);
        lo[j] = packbf(v0 - h0, v1 - h1);
    }
    *(uint4*)&g_Wb[l][0][n * BROW + c] = make_uint4(hi[0], hi[1], hi[2], hi[3]);
    *(uint4*)&g_Wb[l][1][n * BROW + c] = make_uint4(lo[0], lo[1], lo[2], lo[3]);
}

// ===================== L2: fused histogram + scan + dinv + CSR fill =====================
// SF_GRID blocks x 1024 threads, all co-resident -> spin barriers are safe.
__global__ void __launch_bounds__(1024) k_scanfill(const void* edge, int E, int N) {
    __shared__ int ssum[1024];
    __shared__ int sbs[SF_GRID];
    __shared__ int sh_pref, sh_tot;

    int b = blockIdx.x, t = threadIdx.x;
    int is64 = g_is64;
    const long long* e64 = (const long long*)edge;
    const int*       e32 = (const int*)edge;

    // ---- phase 0: degree histogram ----
    for (int e = b * 1024 + t; e < E; e += SF_GRID * 1024) {
        int d = is64 ? (int)e64[E + e] : e32[E + e];
        if ((unsigned)d < (unsigned)N) atomicAdd(&g_deg[d], 1);
    }
    __threadfence();
    __syncthreads();
    if (t == 0) {
        atomicAdd(&g_done0, 1);
        while (atomicAdd(&g_done0, 0) < SF_GRID) __nanosleep(128);
    }
    __syncthreads();

    // ---- phase 1: scan (decoupled lookback) + dinv ----
    int C = (N + SF_GRID - 1) / SF_GRID;       // <= 2048 for N <= 196608
    int base = b * C;
    int lim  = min(base + C, N);
    int i0 = base + 2 * t;                     // consecutive pair (order-correct scan)
    int i1 = i0 + 1;
    int d0 = (i0 < lim) ? g_deg[i0] : 0;
    int d1 = (i1 < lim) ? g_deg[i1] : 0;
    int part = d0 + d1;

    ssum[t] = part;
    __syncthreads();
    for (int off = 1; off < 1024; off <<= 1) {
        int v = (t >= off) ? ssum[t - off] : 0;
        __syncthreads();
        ssum[t] += v;
        __syncthreads();
    }
    int incl = ssum[t];
    int agg  = ssum[1023];

    if (t == 0) atomicExch(&g_blocksum[b], agg);   // publish (atomic => L2-visible)

    if (t < SF_GRID) {
        int v;
        do { v = atomicAdd(&g_blocksum[t], 0); if (v != -1) break; __nanosleep(64); } while (1);
        sbs[t] = v;
    }
    __syncthreads();
    if (t == 0) {
        int p = 0, tot = 0;
        for (int j = 0; j < SF_GRID; j++) { if (j < b) p += sbs[j]; tot += sbs[j]; }
        sh_pref = p; sh_tot = tot;
    }
    __syncthreads();

    int excl = sh_pref + incl - part;          // exclusive prefix of element i0
    if (i0 < lim) {
        g_rptr[i0] = excl;
        atomicExch(&g_cur[i0], excl);          // atomic store: visible to fill phase
        g_dinv[i0] = rsqrtf((float)(d0 + 1));  // +1 self-loop
    }
    if (i1 < lim) {
        int e1 = excl + d0;
        g_rptr[i1] = e1;
        atomicExch(&g_cur[i1], e1);
        g_dinv[i1] = rsqrtf((float)(d1 + 1));
    }
    if (b == SF_GRID - 1 && t == 0) g_rptr[N] = sh_tot;

    __threadfence();
    __syncthreads();
    if (t == 0) {
        atomicAdd(&g_done1, 1);
        while (atomicAdd(&g_done1, 0) < SF_GRID) __nanosleep(128);
    }
    __syncthreads();

    // ---- phase 2: fill (bucket src by dst) ----
    for (int e = b * 1024 + t; e < E; e += SF_GRID * 1024) {
        int s, d;
        if (is64) { s = (int)e64[e]; d = (int)e64[E + e]; }
        else      { s = e32[e];      d = e32[E + e]; }
        if ((unsigned)d < (unsigned)N) {
            int pos = atomicAdd(&g_cur[d], 1);
            g_col[pos] = ((unsigned)s < (unsigned)N) ? s : 0;
        }
    }
}

// ===================== gather: S[d] = dinv[d]*(P[d] + sum_{e:dst=d} P[src]) =====================
template<bool L0>
__global__ void __launch_bounds__(256) k_gather(const float* __restrict__ xin, int N) {
    int w = (blockIdx.x * 256 + threadIdx.x) >> 5;
    if (w >= N) return;
    int lane = threadIdx.x & 31;

    int s0 = g_rptr[w], s1 = g_rptr[w + 1];
    float dv = g_dinv[w];
    const float4* B4 = L0 ? (const float4*)xin : (const float4*)g_P;

    float4 acc = B4[(size_t)w * 32 + lane];       // self term
    if (L0) { acc.x *= dv; acc.y *= dv; acc.z *= dv; acc.w *= dv; }

    int e = s0;
    for (; e + 3 < s1; e += 4) {
        int sa = g_col[e], sb = g_col[e + 1], sc = g_col[e + 2], sd = g_col[e + 3];
        float4 va = B4[(size_t)sa * 32 + lane];
        float4 vb = B4[(size_t)sb * 32 + lane];
        float4 vc = B4[(size_t)sc * 32 + lane];
        float4 vd = B4[(size_t)sd * 32 + lane];
        if (L0) {
            float fa = g_dinv[sa], fb = g_dinv[sb], fc = g_dinv[sc], fd = g_dinv[sd];
            va.x *= fa; va.y *= fa; va.z *= fa; va.w *= fa;
            vb.x *= fb; vb.y *= fb; vb.z *= fb; vb.w *= fb;
            vc.x *= fc; vc.y *= fc; vc.z *= fc; vc.w *= fc;
            vd.x *= fd; vd.y *= fd; vd.z *= fd; vd.w *= fd;
        }
        acc.x += va.x + vb.x + vc.x + vd.x;
        acc.y += va.y + vb.y + vc.y + vd.y;
        acc.z += va.z + vb.z + vc.z + vd.z;
        acc.w += va.w + vb.w + vc.w + vd.w;
    }
    for (; e < s1; e++) {
        int s = g_col[e];
        float4 v = B4[(size_t)s * 32 + lane];
        if (L0) { float f = g_dinv[s]; v.x *= f; v.y *= f; v.z *= f; v.w *= f; }
        acc.x += v.x; acc.y += v.y; acc.z += v.z; acc.w += v.w;
    }

    acc.x *= dv; acc.y *= dv; acc.z *= dv; acc.w *= dv;
    ((float4*)g_S)[(size_t)w * 32 + lane] = acc;
}

// ===================== mma.sync GEMM: out = relu(S @ W + b) =====================
// CTA: 256 threads (8 warps), tile 128x128, K=128. Split bf16 (3 products).
// A-staging uses TRUNCATION split: hi = bits(x)&0xFFFF0000 (exact bf16, packed via PRMT),
// lo = x - hi (exact fp32), packed with one cvt.rn.bf16x2. Same error structure, ~half the instrs.
#define TILE_H (128 * BROW)

__global__ void __launch_bounds__(256, 1) k_gemm_mma(int layer, const float* __restrict__ bias,
                                                     int N) {
    extern __shared__ unsigned short sm[];
    int tid  = threadIdx.x;
    int lane = tid & 31;
    int wid  = tid >> 5;
    int row0 = blockIdx.x * 128;

    unsigned short* Ah = sm;
    unsigned short* Al = sm + TILE_H;
    unsigned short* Bh = sm + 2 * TILE_H;
    unsigned short* Bl = sm + 3 * TILE_H;

    // ---- stage A = g_S: fp32 -> bf16 hi(truncated)/lo ----
#pragma unroll
    for (int i = 0; i < 8; i++) {
        int j = tid + i * 256;
        int r = j >> 4;
        int c = (j & 15) << 3;
        float v[8];
        if (row0 + r < N) {
            float4 a = *(const float4*)(g_S + (size_t)(row0 + r) * 128 + c);
            float4 b = *(const float4*)(g_S + (size_t)(row0 + r) * 128 + c + 4);
            v[0] = a.x; v[1] = a.y; v[2] = a.z; v[3] = a.w;
            v[4] = b.x; v[5] = b.y; v[6] = b.z; v[7] = b.w;
        } else {
#pragma unroll
            for (int q = 0; q < 8; q++) v[q] = 0.f;
        }
        uint32_t hi[4], lo[4];
#pragma unroll
        for (int q = 0; q < 4; q++) {
            float x0 = v[2 * q], x1 = v[2 * q + 1];
            uint32_t u0 = __float_as_uint(x0), u1 = __float_as_uint(x1);
            hi[q] = __byte_perm(u0, u1, 0x7632);   // {hi16(x0), hi16(x1)}
            float l0 = x0 - __uint_as_float(u0 & 0xFFFF0000u);
            float l1 = x1 - __uint_as_float(u1 & 0xFFFF0000u);
            asm("cvt.rn.bf16x2.f32 %0, %1, %2;" : "=r"(lo[q]) : "f"(l1), "f"(l0));
        }
        *(uint4*)&Ah[r * BROW + c] = make_uint4(hi[0], hi[1], hi[2], hi[3]);
        *(uint4*)&Al[r * BROW + c] = make_uint4(lo[0], lo[1], lo[2], lo[3]);
    }

    // ---- copy W images ----
    {
        const uint4* wh = (const uint4*)g_Wb[layer][0];
        const uint4* wl = (const uint4*)g_Wb[layer][1];
        uint4* bh = (uint4*)Bh;
        uint4* bl = (uint4*)Bl;
        for (int j = tid; j < (TILE_H / 8); j += 256) {
            bh[j] = wh[j];
            bl[j] = wl[j];
        }
    }
    __syncthreads();

    int wm = wid & 3;
    int wn = wid >> 2;
    int m0 = wm * 32;
    int n0 = wn * 64;
    int gid = lane >> 2;
    int tig = lane & 3;

    float acc[2][8][4];
#pragma unroll
    for (int mf = 0; mf < 2; mf++)
#pragma unroll
        for (int nf = 0; nf < 8; nf++)
#pragma unroll
            for (int q = 0; q < 4; q++) acc[mf][nf][q] = 0.f;

    for (int s = 0; s < 3; s++) {
        const unsigned short* Asel = (s == 2) ? Al : Ah;
        const unsigned short* Bsel = (s == 1) ? Bl : Bh;
#pragma unroll
        for (int k = 0; k < 8; k++) {
            int k0 = k * 16;
            uint32_t a[2][4];
#pragma unroll
            for (int mf = 0; mf < 2; mf++) {
                int rr = m0 + mf * 16;
                a[mf][0] = *(const uint32_t*)&Asel[(rr + gid)     * BROW + k0 + tig * 2];
                a[mf][1] = *(const uint32_t*)&Asel[(rr + gid + 8) * BROW + k0 + tig * 2];
                a[mf][2] = *(const uint32_t*)&Asel[(rr + gid)     * BROW + k0 + 8 + tig * 2];
                a[mf][3] = *(const uint32_t*)&Asel[(rr + gid + 8) * BROW + k0 + 8 + tig * 2];
            }
            uint32_t b[8][2];
#pragma unroll
            for (int nf = 0; nf < 8; nf++) {
                int n = n0 + nf * 8 + gid;
                b[nf][0] = *(const uint32_t*)&Bsel[n * BROW + k0 + tig * 2];
                b[nf][1] = *(const uint32_t*)&Bsel[n * BROW + k0 + 8 + tig * 2];
            }
#pragma unroll
            for (int mf = 0; mf < 2; mf++)
#pragma unroll
                for (int nf = 0; nf < 8; nf++) {
                    asm volatile(
                        "mma.sync.aligned.m16n8k16.row.col.f32.bf16.bf16.f32 "
                        "{%0,%1,%2,%3}, {%4,%5,%6,%7}, {%8,%9}, {%0,%1,%2,%3};"
                        : "+f"(acc[mf][nf][0]), "+f"(acc[mf][nf][1]),
                          "+f"(acc[mf][nf][2]), "+f"(acc[mf][nf][3])
                        : "r"(a[mf][0]), "r"(a[mf][1]), "r"(a[mf][2]), "r"(a[mf][3]),
                          "r"(b[nf][0]), "r"(b[nf][1]));
                }
        }
    }

    // ---- epilogue: bias + relu; P = out*dinv (layers 0,1) or raw out (layer 2) ----
#pragma unroll
    for (int mf = 0; mf < 2; mf++) {
        int r1 = row0 + m0 + mf * 16 + gid;
        int r2 = r1 + 8;
        float sc1 = 1.f, sc2 = 1.f;
        if (layer < 2) {
            sc1 = (r1 < N) ? g_dinv[r1] : 0.f;
            sc2 = (r2 < N) ? g_dinv[r2] : 0.f;
        }
#pragma unroll
        for (int nf = 0; nf < 8; nf++) {
            int c = n0 + nf * 8 + tig * 2;
            float2 bb = *(const float2*)(bias + c);
            if (r1 < N) {
                float v0 = fmaxf(acc[mf][nf][0] + bb.x, 0.f);
                float v1 = fmaxf(acc[mf][nf][1] + bb.y, 0.f);
                *(float2*)(g_P + (size_t)r1 * 128 + c) = make_float2(v0 * sc1, v1 * sc1);
            }
            if (r2 < N) {
                float v2 = fmaxf(acc[mf][nf][2] + bb.x, 0.f);
                float v3 = fmaxf(acc[mf][nf][3] + bb.y, 0.f);
                *(float2*)(g_P + (size_t)r2 * 128 + c) = make_float2(v2 * sc2, v3 * sc2);
            }
        }
    }
}

// ===================== pooling + output linear (+ zero g_deg for next call) =====================
__global__ void __launch_bounds__(128) k_pool_out(const void* __restrict__ batch,
                                                  const float* __restrict__ out_w,
                                                  const float* __restrict__ out_b,
                                                  float* __restrict__ out, int N) {
    for (int i = blockIdx.x * blockDim.x + threadIdx.x; i < N; i += gridDim.x * blockDim.x)
        g_deg[i] = 0;

    int g = blockIdx.x;
    int d = threadIdx.x;
    int is64 = g_is64;
    const long long* b64 = (const long long*)batch;
    const int*       b32 = (const int*)batch;

    int lo, hi;
    { int a = 0, b = N; while (a < b) { int m = (a + b) >> 1;
        int bm = is64 ? (int)b64[m] : b32[m];
        if (bm < g) a = m + 1; else b = m; } lo = a; }
    { int a = lo, b = N; while (a < b) { int m = (a + b) >> 1;
        int bm = is64 ? (int)b64[m] : b32[m];
        if (bm < g + 1) a = m + 1; else b = m; } hi = a; }

    float s = 0.f, mx = 0.f;   // relu output >= 0: max init 0 matches segment_max for non-empty segments
    for (int n = lo; n < hi; n++) {
        float v = g_P[(size_t)n * 128 + d];   // g_P holds raw H3 after layer 2
        s += v;
        mx = fmaxf(mx, v);
    }
    float cnt  = fmaxf((float)(hi - lo), 1.f);
    float mean = s / cnt;

    __shared__ float sp[128][10];
#pragma unroll
    for (int j = 0; j < 10; j++)
        sp[d][j] = mx * out_w[d * 10 + j]
                 + mean * out_w[(128 + d) * 10 + j]
                 + s * out_w[(256 + d) * 10 + j];
    __syncthreads();

    if (d < 10) {
        float r = 0.f;
        for (int i = 0; i < 128; i++) r += sp[i][d];
        out[g * 10 + d] = r + out_b[d];
    }
}

// ===================== launch =====================
extern "C" void kernel_launch(void* const* d_in, const int* in_sizes, int n_in,
                              void* d_out, int out_size) {
    const float* x      = (const float*)d_in[0];
    const void*  edge   = d_in[1];
    const void*  batch  = d_in[2];
    const float* conv_w = (const float*)d_in[3];
    const float* conv_b = (const float*)d_in[4];
    const float* out_w  = (const float*)d_in[5];
    const float* out_b  = (const float*)d_in[6];
    float*       out    = (float*)d_out;

    int N = in_sizes[0] / 128;
    int E = in_sizes[1] / 2;

    const int SMEM_BYTES = 4 * TILE_H * 2;   // 139264
    static bool attr_done = false;
    if (!attr_done) {
        cudaFuncSetAttribute(k_gemm_mma, cudaFuncAttributeMaxDynamicSharedMemorySize, SMEM_BYTES);
        attr_done = true;
    }

    int tiles = (N + 127) / 128;
    int gblk  = (N * 32 + 255) / 256;

    k_init<<<25, 256>>>(edge, conv_w);                            // 1
    k_scanfill<<<SF_GRID, 1024>>>(edge, E, N);                    // 2 (hist+scan+fill)
    k_gather<true><<<gblk, 256>>>(x, N);                          // 3
    k_gemm_mma<<<tiles, 256, SMEM_BYTES>>>(0, conv_b, N);         // 4  <- profiled
    k_gather<false><<<gblk, 256>>>(nullptr, N);                   // 5
    k_gemm_mma<<<tiles, 256, SMEM_BYTES>>>(1, conv_b + 128, N);   // 6
    k_gather<false><<<gblk, 256>>>(nullptr, N);                   // 7
    k_gemm_mma<<<tiles, 256, SMEM_BYTES>>>(2, conv_b + 256, N);   // 8
    k_pool_out<<<256, 128>>>(batch, out_w, out_b, out, N);        // 9
}